// round 16
// baseline (speedup 1.0000x reference)
#include <cuda_runtime.h>
#include <cuda_fp16.h>
#include <cstdint>
#include <math.h>

// Problem constants
#define S_LEN 2048
#define D_DIM 1024
#define H_NUM 16
#define HD_DIM 64
#define B_NUM 2
#define M_TOT (B_NUM * S_LEN)   // 4096

// log2(e) * (1/sqrt(HD)) : folded into Q at the QKV epilogue
#define Q_PRESCALE 0.180336880f

// Scratch (allocation-free rule: __device__ globals)
__device__ __half g_xh[M_TOT * D_DIM];                    // x, fp16
__device__ __half g_WTh[4 * D_DIM * D_DIM];               // [4096 n][1024 k] K-major fp16
__device__ __half g_Qh[B_NUM * H_NUM * S_LEN * HD_DIM];   // [B,H,S,HD], pre-scaled
__device__ __half g_Kh[B_NUM * H_NUM * S_LEN * HD_DIM];   // [B,H,S,HD]
__device__ __half g_VTh[B_NUM * H_NUM * HD_DIM * S_LEN];  // [B,H,HD,S]  (V transposed)
__device__ __half g_Ctxh[B_NUM * S_LEN * D_DIM];          // merged heads [B,S,D]

// ===========================================================================
// Helpers
// ===========================================================================
__device__ __forceinline__ uint32_t smem_to_u32(const void* smem_ptr) {
    uint32_t addr;
    asm("{ .reg .u64 tmp; cvta.to.shared.u64 tmp, %1; cvt.u32.u64 %0, tmp; }"
        : "=r"(addr) : "l"(smem_ptr));
    return addr;
}
#define CP_ASYNC16(smem_u32, gptr) \
    asm volatile("cp.async.cg.shared.global [%0], [%1], 16;" \
        :: "r"(smem_u32), "l"(gptr) : "memory")
#define CP_COMMIT() asm volatile("cp.async.commit_group;" ::: "memory")
#define CP_WAIT0()  asm volatile("cp.async.wait_group 0;" ::: "memory")

#define LDSM_X4(r0, r1, r2, r3, addr) \
    asm volatile("ldmatrix.sync.aligned.m8n8.x4.shared.b16 {%0,%1,%2,%3}, [%4];" \
        : "=r"(r0), "=r"(r1), "=r"(r2), "=r"(r3) : "r"(addr))

// m16n8k16 fp16 MMA, fp32 accumulate.
__device__ __forceinline__ void mma_f16(float* d,
    uint32_t a0, uint32_t a1, uint32_t a2, uint32_t a3, uint32_t b0, uint32_t b1)
{
    asm volatile(
        "mma.sync.aligned.m16n8k16.row.col.f32.f16.f16.f32 "
        "{%0,%1,%2,%3}, {%4,%5,%6,%7}, {%8,%9}, {%0,%1,%2,%3};"
        : "+f"(d[0]), "+f"(d[1]), "+f"(d[2]), "+f"(d[3])
        : "r"(a0), "r"(a1), "r"(a2), "r"(a3), "r"(b0), "r"(b1));
}

// packed fp16x2 exp2 (one MUFU op for two elements)
__device__ __forceinline__ uint32_t h2exp2(uint32_t x) {
    uint32_t r;
    asm("ex2.approx.f16x2 %0, %1;" : "=r"(r) : "r"(x));
    return r;
}

// ===========================================================================
// Fused prep kernel:
//  blocks [0, 4096)    : cvt x (f32) -> g_xh (fp16), 256 float4 per block
//  blocks [4096, 8192) : transpose W[k][n] -> WTh[n][k] (+fp16), 32x32 tiles
// ===========================================================================
__global__ void prep_kernel(
    const float* __restrict__ xin, __half* __restrict__ xout,
    const float* __restrict__ wq, const float* __restrict__ wk,
    const float* __restrict__ wv, const float* __restrict__ wo,
    __half* __restrict__ WT)
{
    __shared__ float t[32][33];
    const int bidx = blockIdx.x;
    if (bidx < 4096) {
        int i = bidx * 256 + threadIdx.x;       // over float4s (total 1M)
        float4 v = ((const float4*)xin)[i];
        ((__half2*)xout)[2 * i + 0] = __floats2half2_rn(v.x, v.y);
        ((__half2*)xout)[2 * i + 1] = __floats2half2_rn(v.z, v.w);
    } else {
        const int bi = bidx - 4096;
        const int tx = threadIdx.x & 31;
        const int ty = threadIdx.x >> 5;        // 0..7
        const int x = (bi & 31) * 32;           // k tile
        const int y = (bi >> 5) * 32;           // n tile (global, 0..4095)
        const int seg = y >> 10;
        const float* W = (seg == 0) ? wq : (seg == 1) ? wk : (seg == 2) ? wv : wo;
        const int d0 = y & 1023;
        #pragma unroll
        for (int i = 0; i < 4; i++)
            t[ty + i * 8][tx] = W[(size_t)(x + ty + i * 8) * D_DIM + d0 + tx];
        __syncthreads();
        #pragma unroll
        for (int i = 0; i < 4; i++)
            WT[(size_t)(y + ty + i * 8) * D_DIM + x + tx] = __float2half(t[tx][ty + i * 8]);
    }
}

// ===========================================================================
// fp16 mma.sync GEMM with ldmatrix fragment loads.  (round-12 hot path)
// CTA tile 64(M) x 128(N), BK=64 halves, double buffered cp.async.
// 128 threads = 4 warps (2m x 2n), warp tile 32x64, 4 CTAs/SM.
// mode 0: f32 out + bias b0 (output projection)
// mode 3: FUSED QKV, linear grid of 1536 blocks, INTERLEAVED 2:1 so each
//   wave mixes QK CTAs (A=xh, B=WTh) with V^T CTAs (A=WTv, B=xh) — smooths
//   L2 pressure and lets xh tiles serve both streams within a wave.
// ===========================================================================
#define KP 72
#define GA_STAGE (64 * KP)                 // A halves per stage
#define GB_STAGE (128 * KP)                // B halves per stage
#define GEMM_SMEM_BYTES ((2 * GA_STAGE + 2 * GB_STAGE) * 2)   // 55296

__global__ __launch_bounds__(128, 4) void gemm_f16_kernel(
    const __half* __restrict__ A, const __half* __restrict__ Bm,
    const float* __restrict__ b0, const float* __restrict__ b1,
    const float* __restrict__ b2,
    float* __restrict__ outF, __half* __restrict__ outQ, __half* __restrict__ outK,
    __half* __restrict__ outV, int mode)
{
    extern __shared__ __half smh[];
    __half* As = smh;                       // [2][64][KP]
    __half* Bs = smh + 2 * GA_STAGE;        // [2][128][KP]
    const uint32_t as_u32 = smem_to_u32(As);
    const uint32_t bs_u32 = smem_to_u32(Bs);

    const int tid  = threadIdx.x;
    const int wid  = tid >> 5;              // 0..3
    const int lane = tid & 31;

    // ---- decode block -> (sub-mode, operand pointers, tile coords) ----
    int sub, bm, bn;
    const __half *Ap, *Bp;
    if (mode == 0) {
        sub = 0;
        bm = blockIdx.y << 6;
        bn = blockIdx.x << 7;
        Ap = A; Bp = Bm;
    } else {
        const int idx = blockIdx.x;          // 0..1535
        const int tri = idx / 3;             // 0..511
        const int rem = idx - tri * 3;       // 0..2
        if (rem < 2) {                       // QK: 1024 CTAs (2 per triple)
            sub = 1;
            const int q = tri * 2 + rem;     // 0..1023
            bn = (q & 15) << 7;
            bm = (q >> 4) << 6;
            Ap = A;                          // xh
            Bp = Bm;                         // WTh (Q|K segments)
        } else {                             // V^T: 512 CTAs (1 per triple)
            sub = 2;
            bn = (tri & 31) << 7;
            bm = (tri >> 5) << 6;
            Ap = Bm + (size_t)2 * D_DIM * D_DIM;   // WTv
            Bp = A;                          // xh
        }
    }

    const int wm = (wid & 1) << 5;          // 0,32
    const int wn = (wid >> 1) << 6;         // 0,64
    const int fr = lane >> 2;
    const int fc = lane & 3;
    const int lg = lane >> 3;               // ldmatrix matrix group 0..3
    const int lr = lane & 7;                // row within 8x8

    const uint32_t a_off = ((uint32_t)((wm + lr + (lg & 1) * 8) * KP + (lg >> 1) * 8)) * 2;
    const uint32_t b_off = ((uint32_t)((wn + lr + (lg >> 1) * 8) * KP + (lg & 1) * 8)) * 2;

    float acc[2][8][4];
    #pragma unroll
    for (int i = 0; i < 2; i++)
        #pragma unroll
        for (int j = 0; j < 8; j++)
            #pragma unroll
            for (int e = 0; e < 4; e++) acc[i][j][e] = 0.0f;

    #pragma unroll
    for (int it = 0; it < 4; it++) {
        int lin = tid + it * 128;
        int row = lin >> 3;                 // 0..63
        int c8  = (lin & 7) << 3;
        CP_ASYNC16(as_u32 + (row * KP + c8) * 2, Ap + (size_t)(bm + row) * D_DIM + c8);
    }
    #pragma unroll
    for (int it = 0; it < 8; it++) {
        int lin = tid + it * 128;
        int row = lin >> 3;                 // 0..127
        int c8  = (lin & 7) << 3;
        CP_ASYNC16(bs_u32 + (row * KP + c8) * 2, Bp + (size_t)(bn + row) * D_DIM + c8);
    }
    CP_COMMIT();
    CP_WAIT0();
    __syncthreads();

    for (int kt = 0; kt < D_DIM / 64; kt++) {
        const int buf = kt & 1;

        if (kt + 1 < D_DIM / 64) {
            const int k0 = (kt + 1) << 6;
            const uint32_t ad = as_u32 + ((buf ^ 1) * GA_STAGE) * 2;
            const uint32_t bd = bs_u32 + ((buf ^ 1) * GB_STAGE) * 2;
            #pragma unroll
            for (int it = 0; it < 4; it++) {
                int lin = tid + it * 128;
                int row = lin >> 3;
                int c8  = (lin & 7) << 3;
                CP_ASYNC16(ad + (row * KP + c8) * 2, Ap + (size_t)(bm + row) * D_DIM + k0 + c8);
            }
            #pragma unroll
            for (int it = 0; it < 8; it++) {
                int lin = tid + it * 128;
                int row = lin >> 3;
                int c8  = (lin & 7) << 3;
                CP_ASYNC16(bd + (row * KP + c8) * 2, Bp + (size_t)(bn + row) * D_DIM + k0 + c8);
            }
            CP_COMMIT();
        }

        const uint32_t abase = as_u32 + (buf * GA_STAGE) * 2 + a_off;
        const uint32_t bbase = bs_u32 + (buf * GB_STAGE) * 2 + b_off;

        #pragma unroll
        for (int ks = 0; ks < 4; ks++) {
            const uint32_t kofs = (ks << 4) * 2;
            uint32_t af[2][4], bf[8][2];
            #pragma unroll
            for (int i = 0; i < 2; i++)
                LDSM_X4(af[i][0], af[i][1], af[i][2], af[i][3],
                        abase + i * (16 * KP * 2) + kofs);
            #pragma unroll
            for (int p = 0; p < 4; p++)
                LDSM_X4(bf[2 * p][0], bf[2 * p][1], bf[2 * p + 1][0], bf[2 * p + 1][1],
                        bbase + p * (16 * KP * 2) + kofs);
            #pragma unroll
            for (int i = 0; i < 2; i++)
                #pragma unroll
                for (int j = 0; j < 8; j++)
                    mma_f16(acc[i][j], af[i][0], af[i][1], af[i][2], af[i][3],
                            bf[j][0], bf[j][1]);
        }

        CP_WAIT0();
        __syncthreads();
    }

    // ---- epilogue ----
    const int c2 = fc << 1;
    #pragma unroll
    for (int i = 0; i < 2; i++) {
        #pragma unroll
        for (int rr = 0; rr < 2; rr++) {
            const int m = bm + wm + i * 16 + fr + rr * 8;
            #pragma unroll
            for (int j = 0; j < 8; j++) {
                const int n = bn + wn + j * 8 + c2;
                float v0 = acc[i][j][rr * 2 + 0];
                float v1 = acc[i][j][rr * 2 + 1];
                if (sub == 0) {
                    float2 w;
                    w.x = v0 + b0[n + 0];
                    w.y = v1 + b0[n + 1];
                    *(float2*)(outF + (size_t)m * D_DIM + n) = w;
                } else if (sub == 1) {
                    const int b = m >> 11;
                    const int s = m & (S_LEN - 1);
                    const int seg = n >> 10;
                    const int d = n & 1023;
                    const int h = d >> 6;
                    const int hd = d & 63;
                    size_t idx = (((size_t)(b * H_NUM + h) * S_LEN + s) << 6) + hd;
                    if (seg == 0) {
                        *(__half2*)(outQ + idx) = __floats2half2_rn(
                            (v0 + b0[d]) * Q_PRESCALE, (v1 + b0[d + 1]) * Q_PRESCALE);
                    } else {
                        *(__half2*)(outK + idx) = __floats2half2_rn(v0 + b1[d], v1 + b1[d + 1]);
                    }
                } else {
                    // sub 2: m = feature d (0..1023), n = sequence index
                    const float bias = b2[m];
                    const int h = m >> 6;
                    const int hd = m & 63;
                    const int b = n >> 11;
                    const int s = n & (S_LEN - 1);
                    size_t idx = (((size_t)(b * H_NUM + h) * HD_DIM + hd) << 11) + s;
                    *(__half2*)(outV + idx) = __floats2half2_rn(v0 + bias, v1 + bias);
                }
            }
        }
    }
}

// ===========================================================================
// Flash attention (causal), fp16 mma + ldmatrix, Br=64, Bc=64, 128 threads,
// 4 CTAs/SM. Warp w owns q-rows [16w,16w+16) x all 64 kv cols; register P.
// Softmax exponentials via ex2.approx.f16x2.  (round-12/15 configuration)
// ===========================================================================
#define F_TILE (64 * KP)
#define FLASH_SMEM_BYTES (4 * F_TILE * 2)         // 36864 B

__global__ __launch_bounds__(128, 4) void flash_f16_kernel(
    const __half* __restrict__ Q, const __half* __restrict__ K,
    const __half* __restrict__ VT, __half* __restrict__ Out)
{
    extern __shared__ __half smh[];
    __half* Ks  = smh;                   // [2][64][KP]
    __half* VTs = smh + 2 * F_TILE;      // [2][64][KP]
    const uint32_t ks_u32  = smem_to_u32(Ks);
    const uint32_t vts_u32 = smem_to_u32(VTs);

    const int tid  = threadIdx.x;
    const int lane = tid & 31;
    const int w    = tid >> 5;           // 0..3
    const int fr = lane >> 2;
    const int fc = lane & 3;
    const int lg = lane >> 3;
    const int lr = lane & 7;
    const int qb = gridDim.x - 1 - blockIdx.x;   // heavy blocks first
    const int bh = blockIdx.y;
    const int q0 = qb * 64;

    const __half* Qg = Q  + ((size_t)bh * S_LEN + q0) * HD_DIM;
    const __half* Kg = K  + (size_t)bh * S_LEN * HD_DIM;
    const __half* Vg = VT + (size_t)bh * HD_DIM * S_LEN;

    const uint32_t qa_off = ((uint32_t)((16 * w + lr + (lg & 1) * 8) * KP + (lg >> 1) * 8)) * 2;
    const uint32_t kb_off = ((uint32_t)((lr + (lg >> 1) * 8) * KP + (lg & 1) * 8)) * 2;

    // ---- stage Q tile [64][64] through Ks, extract frags via ldmatrix ----
    #pragma unroll
    for (int it = 0; it < 4; it++) {
        int lin = tid + it * 128;
        int row = lin >> 3;
        int c8  = (lin & 7) << 3;
        CP_ASYNC16(ks_u32 + (row * KP + c8) * 2, Qg + row * HD_DIM + c8);
    }
    CP_COMMIT();
    CP_WAIT0();
    __syncthreads();

    uint32_t qf[4][4];
    #pragma unroll
    for (int ks = 0; ks < 4; ks++)
        LDSM_X4(qf[ks][0], qf[ks][1], qf[ks][2], qf[ks][3],
                ks_u32 + qa_off + (ks << 4) * 2);
    __syncthreads();

    // ---- prologue: K/VT tile 0 -> buf 0 ----
    #pragma unroll
    for (int it = 0; it < 4; it++) {
        int lin = tid + it * 128;
        int row = lin >> 3;
        int c8  = (lin & 7) << 3;
        CP_ASYNC16(ks_u32  + (row * KP + c8) * 2, Kg + row * HD_DIM + c8);
        CP_ASYNC16(vts_u32 + (row * KP + c8) * 2, Vg + (size_t)row * S_LEN + c8);
    }
    CP_COMMIT();

    float mI[2] = {-1e30f, -1e30f};
    float lI[2] = {0.0f, 0.0f};
    float o[8][4];
    #pragma unroll
    for (int j = 0; j < 8; j++)
        #pragma unroll
        for (int e = 0; e < 4; e++) o[j][e] = 0.0f;

    for (int t = 0; t <= qb; t++) {
        const int buf = t & 1;
        CP_WAIT0();
        __syncthreads();

        if (t < qb) {
            const __half* Kt = Kg + (size_t)(t + 1) * 64 * HD_DIM;
            const __half* Vt = Vg + (size_t)(t + 1) * 64;
            const uint32_t kd = ks_u32  + ((buf ^ 1) * F_TILE) * 2;
            const uint32_t vd = vts_u32 + ((buf ^ 1) * F_TILE) * 2;
            #pragma unroll
            for (int it = 0; it < 4; it++) {
                int lin = tid + it * 128;
                int row = lin >> 3;
                int c8  = (lin & 7) << 3;
                CP_ASYNC16(kd + (row * KP + c8) * 2, Kt + row * HD_DIM + c8);
                CP_ASYNC16(vd + (row * KP + c8) * 2, Vt + (size_t)row * S_LEN + c8);
            }
            CP_COMMIT();
        }

        const uint32_t kbase = ks_u32  + (buf * F_TILE) * 2 + kb_off;
        const uint32_t vbase = vts_u32 + (buf * F_TILE) * 2 + kb_off;
        float s[8][4];

        if (t < qb) {
            // ---- interior tile: fully unrolled ----
            #pragma unroll
            for (int j = 0; j < 8; j++)
                #pragma unroll
                for (int e = 0; e < 4; e++) s[j][e] = 0.0f;
            #pragma unroll
            for (int ks = 0; ks < 4; ks++) {
                const uint32_t kofs = (ks << 4) * 2;
                #pragma unroll
                for (int p = 0; p < 4; p++) {
                    uint32_t b0, b1, b2, b3;
                    LDSM_X4(b0, b1, b2, b3, kbase + p * (16 * KP * 2) + kofs);
                    mma_f16(s[2 * p],     qf[ks][0], qf[ks][1], qf[ks][2], qf[ks][3], b0, b1);
                    mma_f16(s[2 * p + 1], qf[ks][0], qf[ks][1], qf[ks][2], qf[ks][3], b2, b3);
                }
            }
        } else {
            // ---- diagonal tile: pair-trimmed + masked (pairs 0..w alive) ----
            #pragma unroll
            for (int j = 0; j < 8; j++)
                #pragma unroll
                for (int e = 0; e < 4; e++) s[j][e] = -1e30f;
            for (int p = 0; p <= w; p++)
                #pragma unroll
                for (int e = 0; e < 4; e++) {
                    s[2 * p][e] = 0.0f;
                    s[2 * p + 1][e] = 0.0f;
                }
            #pragma unroll
            for (int ks = 0; ks < 4; ks++) {
                const uint32_t kofs = (ks << 4) * 2;
                for (int p = 0; p <= w; p++) {
                    uint32_t b0, b1, b2, b3;
                    LDSM_X4(b0, b1, b2, b3, kbase + p * (16 * KP * 2) + kofs);
                    mma_f16(s[2 * p],     qf[ks][0], qf[ks][1], qf[ks][2], qf[ks][3], b0, b1);
                    mma_f16(s[2 * p + 1], qf[ks][0], qf[ks][1], qf[ks][2], qf[ks][3], b2, b3);
                }
            }
            #pragma unroll
            for (int j = 0; j < 8; j++)
                #pragma unroll
                for (int e = 0; e < 4; e++) {
                    int col = 8 * j + 2 * fc + (e & 1);
                    int row = 16 * w + fr + 8 * (e >> 1);
                    if (col > row) s[j][e] = -1e30f;
                }
        }

        // ---- in-register online softmax (base-2, packed fp16x2 exp2) ----
        uint32_t ph[8][2];
        float facr[2];
        #pragma unroll
        for (int h = 0; h < 2; h++) {
            float rm = fmaxf(s[0][2 * h], s[0][2 * h + 1]);
            #pragma unroll
            for (int j = 1; j < 8; j++)
                rm = fmaxf(rm, fmaxf(s[j][2 * h], s[j][2 * h + 1]));
            rm = fmaxf(rm, __shfl_xor_sync(0xffffffffu, rm, 1));
            rm = fmaxf(rm, __shfl_xor_sync(0xffffffffu, rm, 2));
            float mnew = fmaxf(mI[h], rm);
            facr[h] = exp2f(mI[h] - mnew);
            mI[h] = mnew;

            float rs = 0.0f;
            #pragma unroll
            for (int j = 0; j < 8; j++) {
                __half2 xh2 = __floats2half2_rn(s[j][2 * h] - mnew,
                                                s[j][2 * h + 1] - mnew);
                uint32_t px = h2exp2(*(uint32_t*)&xh2);
                ph[j][h] = px;
                float2 pf = __half22float2(*(__half2*)&px);
                rs += pf.x + pf.y;
            }
            rs += __shfl_xor_sync(0xffffffffu, rs, 1);
            rs += __shfl_xor_sync(0xffffffffu, rs, 2);
            lI[h] = lI[h] * facr[h] + rs;
        }

        // ---- rescale O, then O += P V (fully unrolled, ldmatrix B) ----
        #pragma unroll
        for (int j = 0; j < 8; j++) {
            o[j][0] *= facr[0]; o[j][1] *= facr[0];
            o[j][2] *= facr[1]; o[j][3] *= facr[1];
        }
        #pragma unroll
        for (int kc = 0; kc < 4; kc++) {
            const uint32_t kofs = (kc << 4) * 2;
            uint32_t a0 = ph[2 * kc][0],     a1 = ph[2 * kc][1];
            uint32_t a2 = ph[2 * kc + 1][0], a3 = ph[2 * kc + 1][1];
            #pragma unroll
            for (int p = 0; p < 4; p++) {
                uint32_t b0, b1, b2, b3;
                LDSM_X4(b0, b1, b2, b3, vbase + p * (16 * KP * 2) + kofs);
                mma_f16(o[2 * p],     a0, a1, a2, a3, b0, b1);
                mma_f16(o[2 * p + 1], a0, a1, a2, a3, b2, b3);
            }
        }
    }

    // ---- epilogue: Ctxh[b][q][h*64+hd] = half(o / l) ----
    const int b  = bh >> 4;
    const int hh = bh & 15;
    #pragma unroll
    for (int h = 0; h < 2; h++) {
        const float inv = 1.0f / lI[h];
        const int qrow = q0 + 16 * w + fr + 8 * h;
        __half* dst = Out + ((size_t)(b * S_LEN + qrow)) * D_DIM + hh * HD_DIM;
        #pragma unroll
        for (int jh = 0; jh < 8; jh++) {
            __half2 v = __floats2half2_rn(o[jh][2 * h] * inv, o[jh][2 * h + 1] * inv);
            *(__half2*)&dst[8 * jh + 2 * fc] = v;
        }
    }
}

// ---------------------------------------------------------------------------
// Launch
// ---------------------------------------------------------------------------
extern "C" void kernel_launch(void* const* d_in, const int* in_sizes, int n_in,
                              void* d_out, int out_size)
{
    const float* x  = (const float*)d_in[0];
    // d_in[1] = mask — reproduced analytically in-kernel
    const float* wq = (const float*)d_in[2];
    const float* bq = (const float*)d_in[3];
    const float* wk = (const float*)d_in[4];
    const float* bk = (const float*)d_in[5];
    const float* wv = (const float*)d_in[6];
    const float* bv = (const float*)d_in[7];
    const float* wo = (const float*)d_in[8];
    const float* bo = (const float*)d_in[9];
    float* out = (float*)d_out;

    __half *xh, *wth, *Qh, *Kh, *VTh, *Ctxh;
    cudaGetSymbolAddress((void**)&xh,   g_xh);
    cudaGetSymbolAddress((void**)&wth,  g_WTh);
    cudaGetSymbolAddress((void**)&Qh,   g_Qh);
    cudaGetSymbolAddress((void**)&Kh,   g_Kh);
    cudaGetSymbolAddress((void**)&VTh,  g_VTh);
    cudaGetSymbolAddress((void**)&Ctxh, g_Ctxh);

    cudaFuncSetAttribute(gemm_f16_kernel,
                         cudaFuncAttributeMaxDynamicSharedMemorySize,
                         GEMM_SMEM_BYTES);
    cudaFuncSetAttribute(flash_f16_kernel,
                         cudaFuncAttributeMaxDynamicSharedMemorySize,
                         FLASH_SMEM_BYTES);

    // 1. fused prep: x -> fp16  +  weight transpose -> fp16
    prep_kernel<<<8192, 256>>>(x, xh, wq, wk, wv, wo, wth);

    // 2. fused QKV projection in ONE launch (1536 CTAs, QK/V^T interleaved 2:1)
    gemm_f16_kernel<<<1536, 128, GEMM_SMEM_BYTES>>>(
        xh, wth, bq, bk, bv, nullptr, Qh, Kh, VTh, 3);

    // 3. attention (fp16 flash, 4 CTAs/SM, ldmatrix, f16x2 exp2)
    flash_f16_kernel<<<dim3(S_LEN / 64, B_NUM * H_NUM), 128, FLASH_SMEM_BYTES>>>(
        Qh, Kh, VTh, Ctxh);

    // 4. output projection (f32 out)
    gemm_f16_kernel<<<dim3(D_DIM / 128, M_TOT / 64), 128, GEMM_SMEM_BYTES>>>(
        Ctxh, wth + (size_t)3 * D_DIM * D_DIM, bo, nullptr, nullptr,
        out, nullptr, nullptr, nullptr, 0);
}

// round 17
// speedup vs baseline: 1.0511x; 1.0511x over previous
#include <cuda_runtime.h>
#include <cuda_fp16.h>
#include <cstdint>
#include <math.h>

// Problem constants
#define S_LEN 2048
#define D_DIM 1024
#define H_NUM 16
#define HD_DIM 64
#define B_NUM 2
#define M_TOT (B_NUM * S_LEN)   // 4096

// log2(e) * (1/sqrt(HD)) : folded into Q at the QKV epilogue
#define Q_PRESCALE 0.180336880f

// Scratch (allocation-free rule: __device__ globals)
__device__ __half g_xh[M_TOT * D_DIM];                    // x, fp16
__device__ __half g_WTh[4 * D_DIM * D_DIM];               // [4096 n][1024 k] K-major fp16
__device__ __half g_Qh[B_NUM * H_NUM * S_LEN * HD_DIM];   // [B,H,S,HD], pre-scaled
__device__ __half g_Kh[B_NUM * H_NUM * S_LEN * HD_DIM];   // [B,H,S,HD]
__device__ __half g_VTh[B_NUM * H_NUM * HD_DIM * S_LEN];  // [B,H,HD,S]  (V transposed)
__device__ __half g_Ctxh[B_NUM * S_LEN * D_DIM];          // merged heads [B,S,D]

// ===========================================================================
// Helpers
// ===========================================================================
__device__ __forceinline__ uint32_t smem_to_u32(const void* smem_ptr) {
    uint32_t addr;
    asm("{ .reg .u64 tmp; cvta.to.shared.u64 tmp, %1; cvt.u32.u64 %0, tmp; }"
        : "=r"(addr) : "l"(smem_ptr));
    return addr;
}
#define CP_ASYNC16(smem_u32, gptr) \
    asm volatile("cp.async.cg.shared.global [%0], [%1], 16;" \
        :: "r"(smem_u32), "l"(gptr) : "memory")
#define CP_COMMIT() asm volatile("cp.async.commit_group;" ::: "memory")
#define CP_WAIT0()  asm volatile("cp.async.wait_group 0;" ::: "memory")

#define LDSM_X4(r0, r1, r2, r3, addr) \
    asm volatile("ldmatrix.sync.aligned.m8n8.x4.shared.b16 {%0,%1,%2,%3}, [%4];" \
        : "=r"(r0), "=r"(r1), "=r"(r2), "=r"(r3) : "r"(addr))

// m16n8k16 fp16 MMA, fp32 accumulate.
__device__ __forceinline__ void mma_f16(float* d,
    uint32_t a0, uint32_t a1, uint32_t a2, uint32_t a3, uint32_t b0, uint32_t b1)
{
    asm volatile(
        "mma.sync.aligned.m16n8k16.row.col.f32.f16.f16.f32 "
        "{%0,%1,%2,%3}, {%4,%5,%6,%7}, {%8,%9}, {%0,%1,%2,%3};"
        : "+f"(d[0]), "+f"(d[1]), "+f"(d[2]), "+f"(d[3])
        : "r"(a0), "r"(a1), "r"(a2), "r"(a3), "r"(b0), "r"(b1));
}

// packed fp16x2 exp2 (one MUFU op for two elements)
__device__ __forceinline__ uint32_t h2exp2(uint32_t x) {
    uint32_t r;
    asm("ex2.approx.f16x2 %0, %1;" : "=r"(r) : "r"(x));
    return r;
}

// ===========================================================================
// Fused prep kernel:
//  blocks [0, 4096)    : cvt x (f32) -> g_xh (fp16), 256 float4 per block
//  blocks [4096, 8192) : transpose W[k][n] -> WTh[n][k] (+fp16), 32x32 tiles
// ===========================================================================
__global__ void prep_kernel(
    const float* __restrict__ xin, __half* __restrict__ xout,
    const float* __restrict__ wq, const float* __restrict__ wk,
    const float* __restrict__ wv, const float* __restrict__ wo,
    __half* __restrict__ WT)
{
    __shared__ float t[32][33];
    const int bidx = blockIdx.x;
    if (bidx < 4096) {
        int i = bidx * 256 + threadIdx.x;       // over float4s (total 1M)
        float4 v = ((const float4*)xin)[i];
        ((__half2*)xout)[2 * i + 0] = __floats2half2_rn(v.x, v.y);
        ((__half2*)xout)[2 * i + 1] = __floats2half2_rn(v.z, v.w);
    } else {
        const int bi = bidx - 4096;
        const int tx = threadIdx.x & 31;
        const int ty = threadIdx.x >> 5;        // 0..7
        const int x = (bi & 31) * 32;           // k tile
        const int y = (bi >> 5) * 32;           // n tile (global, 0..4095)
        const int seg = y >> 10;
        const float* W = (seg == 0) ? wq : (seg == 1) ? wk : (seg == 2) ? wv : wo;
        const int d0 = y & 1023;
        #pragma unroll
        for (int i = 0; i < 4; i++)
            t[ty + i * 8][tx] = W[(size_t)(x + ty + i * 8) * D_DIM + d0 + tx];
        __syncthreads();
        #pragma unroll
        for (int i = 0; i < 4; i++)
            WT[(size_t)(y + ty + i * 8) * D_DIM + x + tx] = __float2half(t[tx][ty + i * 8]);
    }
}

// ===========================================================================
// fp16 mma.sync GEMM with ldmatrix fragment loads.  (round-12 configuration)
// CTA tile 64(M) x 128(N), BK=64 halves, double buffered cp.async.
// 128 threads = 4 warps (2m x 2n), warp tile 32x64, 4 CTAs/SM.
// mode 0: f32 out + bias b0 (output projection)
// mode 3: FUSED QKV, linear grid of 1536 blocks (QK + swapped-operand V^T)
// ===========================================================================
#define KP 72
#define GA_STAGE (64 * KP)                 // A halves per stage
#define GB_STAGE (128 * KP)                // B halves per stage
#define GEMM_SMEM_BYTES ((2 * GA_STAGE + 2 * GB_STAGE) * 2)   // 55296

__global__ __launch_bounds__(128, 4) void gemm_f16_kernel(
    const __half* __restrict__ A, const __half* __restrict__ Bm,
    const float* __restrict__ b0, const float* __restrict__ b1,
    const float* __restrict__ b2,
    float* __restrict__ outF, __half* __restrict__ outQ, __half* __restrict__ outK,
    __half* __restrict__ outV, int mode)
{
    extern __shared__ __half smh[];
    __half* As = smh;                       // [2][64][KP]
    __half* Bs = smh + 2 * GA_STAGE;        // [2][128][KP]
    const uint32_t as_u32 = smem_to_u32(As);
    const uint32_t bs_u32 = smem_to_u32(Bs);

    const int tid  = threadIdx.x;
    const int wid  = tid >> 5;              // 0..3
    const int lane = tid & 31;

    // ---- decode block -> (sub-mode, operand pointers, tile coords) ----
    int sub, bm, bn;
    const __half *Ap, *Bp;
    if (mode == 0) {
        sub = 0;
        bm = blockIdx.y << 6;
        bn = blockIdx.x << 7;
        Ap = A; Bp = Bm;
    } else {
        const int idx = blockIdx.x;
        if (idx < 1024) {                  // QK: N=2048, M=4096
            sub = 1;
            bn = (idx & 15) << 7;
            bm = (idx >> 4) << 6;
            Ap = A;                        // xh
            Bp = Bm;                       // WTh (Q|K segments)
        } else {                           // V^T: "N"=4096 (seq), "M"=1024 (feat)
            sub = 2;
            const int i2 = idx - 1024;
            bn = (i2 & 31) << 7;
            bm = (i2 >> 5) << 6;
            Ap = Bm + (size_t)2 * D_DIM * D_DIM;   // WTv
            Bp = A;                        // xh
        }
    }

    const int wm = (wid & 1) << 5;          // 0,32
    const int wn = (wid >> 1) << 6;         // 0,64
    const int fr = lane >> 2;
    const int fc = lane & 3;
    const int lg = lane >> 3;               // ldmatrix matrix group 0..3
    const int lr = lane & 7;                // row within 8x8

    const uint32_t a_off = ((uint32_t)((wm + lr + (lg & 1) * 8) * KP + (lg >> 1) * 8)) * 2;
    const uint32_t b_off = ((uint32_t)((wn + lr + (lg >> 1) * 8) * KP + (lg & 1) * 8)) * 2;

    float acc[2][8][4];
    #pragma unroll
    for (int i = 0; i < 2; i++)
        #pragma unroll
        for (int j = 0; j < 8; j++)
            #pragma unroll
            for (int e = 0; e < 4; e++) acc[i][j][e] = 0.0f;

    #pragma unroll
    for (int it = 0; it < 4; it++) {
        int lin = tid + it * 128;
        int row = lin >> 3;                 // 0..63
        int c8  = (lin & 7) << 3;
        CP_ASYNC16(as_u32 + (row * KP + c8) * 2, Ap + (size_t)(bm + row) * D_DIM + c8);
    }
    #pragma unroll
    for (int it = 0; it < 8; it++) {
        int lin = tid + it * 128;
        int row = lin >> 3;                 // 0..127
        int c8  = (lin & 7) << 3;
        CP_ASYNC16(bs_u32 + (row * KP + c8) * 2, Bp + (size_t)(bn + row) * D_DIM + c8);
    }
    CP_COMMIT();
    CP_WAIT0();
    __syncthreads();

    for (int kt = 0; kt < D_DIM / 64; kt++) {
        const int buf = kt & 1;

        if (kt + 1 < D_DIM / 64) {
            const int k0 = (kt + 1) << 6;
            const uint32_t ad = as_u32 + ((buf ^ 1) * GA_STAGE) * 2;
            const uint32_t bd = bs_u32 + ((buf ^ 1) * GB_STAGE) * 2;
            #pragma unroll
            for (int it = 0; it < 4; it++) {
                int lin = tid + it * 128;
                int row = lin >> 3;
                int c8  = (lin & 7) << 3;
                CP_ASYNC16(ad + (row * KP + c8) * 2, Ap + (size_t)(bm + row) * D_DIM + k0 + c8);
            }
            #pragma unroll
            for (int it = 0; it < 8; it++) {
                int lin = tid + it * 128;
                int row = lin >> 3;
                int c8  = (lin & 7) << 3;
                CP_ASYNC16(bd + (row * KP + c8) * 2, Bp + (size_t)(bn + row) * D_DIM + k0 + c8);
            }
            CP_COMMIT();
        }

        const uint32_t abase = as_u32 + (buf * GA_STAGE) * 2 + a_off;
        const uint32_t bbase = bs_u32 + (buf * GB_STAGE) * 2 + b_off;

        #pragma unroll
        for (int ks = 0; ks < 4; ks++) {
            const uint32_t kofs = (ks << 4) * 2;
            uint32_t af[2][4], bf[8][2];
            #pragma unroll
            for (int i = 0; i < 2; i++)
                LDSM_X4(af[i][0], af[i][1], af[i][2], af[i][3],
                        abase + i * (16 * KP * 2) + kofs);
            #pragma unroll
            for (int p = 0; p < 4; p++)
                LDSM_X4(bf[2 * p][0], bf[2 * p][1], bf[2 * p + 1][0], bf[2 * p + 1][1],
                        bbase + p * (16 * KP * 2) + kofs);
            #pragma unroll
            for (int i = 0; i < 2; i++)
                #pragma unroll
                for (int j = 0; j < 8; j++)
                    mma_f16(acc[i][j], af[i][0], af[i][1], af[i][2], af[i][3],
                            bf[j][0], bf[j][1]);
        }

        if (kt + 1 < D_DIM / 64) CP_WAIT0();
        __syncthreads();
    }

    // ---- epilogue ----
    const int c2 = fc << 1;
    #pragma unroll
    for (int i = 0; i < 2; i++) {
        #pragma unroll
        for (int rr = 0; rr < 2; rr++) {
            const int m = bm + wm + i * 16 + fr + rr * 8;
            #pragma unroll
            for (int j = 0; j < 8; j++) {
                const int n = bn + wn + j * 8 + c2;
                float v0 = acc[i][j][rr * 2 + 0];
                float v1 = acc[i][j][rr * 2 + 1];
                if (sub == 0) {
                    float2 w;
                    w.x = v0 + b0[n + 0];
                    w.y = v1 + b0[n + 1];
                    *(float2*)(outF + (size_t)m * D_DIM + n) = w;
                } else if (sub == 1) {
                    const int b = m >> 11;
                    const int s = m & (S_LEN - 1);
                    const int seg = n >> 10;
                    const int d = n & 1023;
                    const int h = d >> 6;
                    const int hd = d & 63;
                    size_t idx = (((size_t)(b * H_NUM + h) * S_LEN + s) << 6) + hd;
                    if (seg == 0) {
                        *(__half2*)(outQ + idx) = __floats2half2_rn(
                            (v0 + b0[d]) * Q_PRESCALE, (v1 + b0[d + 1]) * Q_PRESCALE);
                    } else {
                        *(__half2*)(outK + idx) = __floats2half2_rn(v0 + b1[d], v1 + b1[d + 1]);
                    }
                } else {
                    // sub 2: m = feature d (0..1023), n = sequence index
                    const float bias = b2[m];
                    const int h = m >> 6;
                    const int hd = m & 63;
                    const int b = n >> 11;
                    const int s = n & (S_LEN - 1);
                    size_t idx = (((size_t)(b * H_NUM + h) * HD_DIM + hd) << 11) + s;
                    *(__half2*)(outV + idx) = __floats2half2_rn(v0 + bias, v1 + bias);
                }
            }
        }
    }
}

// ===========================================================================
// Flash attention (causal), fp16 mma + ldmatrix, Br=64, Bc=64, 128 threads,
// 4 CTAs/SM. Warp w owns q-rows [16w,16w+16) x all 64 kv cols; register P.
// Softmax exponentials via ex2.approx.f16x2.  (round-12 configuration)
// ===========================================================================
#define F_TILE (64 * KP)
#define FLASH_SMEM_BYTES (4 * F_TILE * 2)         // 36864 B

__global__ __launch_bounds__(128, 4) void flash_f16_kernel(
    const __half* __restrict__ Q, const __half* __restrict__ K,
    const __half* __restrict__ VT, __half* __restrict__ Out)
{
    extern __shared__ __half smh[];
    __half* Ks  = smh;                   // [2][64][KP]
    __half* VTs = smh + 2 * F_TILE;      // [2][64][KP]
    const uint32_t ks_u32  = smem_to_u32(Ks);
    const uint32_t vts_u32 = smem_to_u32(VTs);

    const int tid  = threadIdx.x;
    const int lane = tid & 31;
    const int w    = tid >> 5;           // 0..3
    const int fr = lane >> 2;
    const int fc = lane & 3;
    const int lg = lane >> 3;
    const int lr = lane & 7;
    const int qb = gridDim.x - 1 - blockIdx.x;   // heavy blocks first
    const int bh = blockIdx.y;
    const int q0 = qb * 64;

    const __half* Qg = Q  + ((size_t)bh * S_LEN + q0) * HD_DIM;
    const __half* Kg = K  + (size_t)bh * S_LEN * HD_DIM;
    const __half* Vg = VT + (size_t)bh * HD_DIM * S_LEN;

    const uint32_t qa_off = ((uint32_t)((16 * w + lr + (lg & 1) * 8) * KP + (lg >> 1) * 8)) * 2;
    const uint32_t kb_off = ((uint32_t)((lr + (lg >> 1) * 8) * KP + (lg & 1) * 8)) * 2;

    // ---- stage Q tile [64][64] through Ks, extract frags via ldmatrix ----
    #pragma unroll
    for (int it = 0; it < 4; it++) {
        int lin = tid + it * 128;
        int row = lin >> 3;
        int c8  = (lin & 7) << 3;
        CP_ASYNC16(ks_u32 + (row * KP + c8) * 2, Qg + row * HD_DIM + c8);
    }
    CP_COMMIT();
    CP_WAIT0();
    __syncthreads();

    uint32_t qf[4][4];
    #pragma unroll
    for (int ks = 0; ks < 4; ks++)
        LDSM_X4(qf[ks][0], qf[ks][1], qf[ks][2], qf[ks][3],
                ks_u32 + qa_off + (ks << 4) * 2);
    __syncthreads();

    // ---- prologue: K/VT tile 0 -> buf 0 ----
    #pragma unroll
    for (int it = 0; it < 4; it++) {
        int lin = tid + it * 128;
        int row = lin >> 3;
        int c8  = (lin & 7) << 3;
        CP_ASYNC16(ks_u32  + (row * KP + c8) * 2, Kg + row * HD_DIM + c8);
        CP_ASYNC16(vts_u32 + (row * KP + c8) * 2, Vg + (size_t)row * S_LEN + c8);
    }
    CP_COMMIT();

    float mI[2] = {-1e30f, -1e30f};
    float lI[2] = {0.0f, 0.0f};
    float o[8][4];
    #pragma unroll
    for (int j = 0; j < 8; j++)
        #pragma unroll
        for (int e = 0; e < 4; e++) o[j][e] = 0.0f;

    for (int t = 0; t <= qb; t++) {
        const int buf = t & 1;
        CP_WAIT0();
        __syncthreads();

        if (t < qb) {
            const __half* Kt = Kg + (size_t)(t + 1) * 64 * HD_DIM;
            const __half* Vt = Vg + (size_t)(t + 1) * 64;
            const uint32_t kd = ks_u32  + ((buf ^ 1) * F_TILE) * 2;
            const uint32_t vd = vts_u32 + ((buf ^ 1) * F_TILE) * 2;
            #pragma unroll
            for (int it = 0; it < 4; it++) {
                int lin = tid + it * 128;
                int row = lin >> 3;
                int c8  = (lin & 7) << 3;
                CP_ASYNC16(kd + (row * KP + c8) * 2, Kt + row * HD_DIM + c8);
                CP_ASYNC16(vd + (row * KP + c8) * 2, Vt + (size_t)row * S_LEN + c8);
            }
            CP_COMMIT();
        }

        const uint32_t kbase = ks_u32  + (buf * F_TILE) * 2 + kb_off;
        const uint32_t vbase = vts_u32 + (buf * F_TILE) * 2 + kb_off;
        float s[8][4];

        if (t < qb) {
            // ---- interior tile: fully unrolled ----
            #pragma unroll
            for (int j = 0; j < 8; j++)
                #pragma unroll
                for (int e = 0; e < 4; e++) s[j][e] = 0.0f;
            #pragma unroll
            for (int ks = 0; ks < 4; ks++) {
                const uint32_t kofs = (ks << 4) * 2;
                #pragma unroll
                for (int p = 0; p < 4; p++) {
                    uint32_t b0, b1, b2, b3;
                    LDSM_X4(b0, b1, b2, b3, kbase + p * (16 * KP * 2) + kofs);
                    mma_f16(s[2 * p],     qf[ks][0], qf[ks][1], qf[ks][2], qf[ks][3], b0, b1);
                    mma_f16(s[2 * p + 1], qf[ks][0], qf[ks][1], qf[ks][2], qf[ks][3], b2, b3);
                }
            }
        } else {
            // ---- diagonal tile: pair-trimmed + masked (pairs 0..w alive) ----
            #pragma unroll
            for (int j = 0; j < 8; j++)
                #pragma unroll
                for (int e = 0; e < 4; e++) s[j][e] = -1e30f;
            for (int p = 0; p <= w; p++)
                #pragma unroll
                for (int e = 0; e < 4; e++) {
                    s[2 * p][e] = 0.0f;
                    s[2 * p + 1][e] = 0.0f;
                }
            #pragma unroll
            for (int ks = 0; ks < 4; ks++) {
                const uint32_t kofs = (ks << 4) * 2;
                for (int p = 0; p <= w; p++) {
                    uint32_t b0, b1, b2, b3;
                    LDSM_X4(b0, b1, b2, b3, kbase + p * (16 * KP * 2) + kofs);
                    mma_f16(s[2 * p],     qf[ks][0], qf[ks][1], qf[ks][2], qf[ks][3], b0, b1);
                    mma_f16(s[2 * p + 1], qf[ks][0], qf[ks][1], qf[ks][2], qf[ks][3], b2, b3);
                }
            }
            #pragma unroll
            for (int j = 0; j < 8; j++)
                #pragma unroll
                for (int e = 0; e < 4; e++) {
                    int col = 8 * j + 2 * fc + (e & 1);
                    int row = 16 * w + fr + 8 * (e >> 1);
                    if (col > row) s[j][e] = -1e30f;
                }
        }

        // ---- in-register online softmax (base-2, packed fp16x2 exp2) ----
        uint32_t ph[8][2];
        float facr[2];
        #pragma unroll
        for (int h = 0; h < 2; h++) {
            float rm = fmaxf(s[0][2 * h], s[0][2 * h + 1]);
            #pragma unroll
            for (int j = 1; j < 8; j++)
                rm = fmaxf(rm, fmaxf(s[j][2 * h], s[j][2 * h + 1]));
            rm = fmaxf(rm, __shfl_xor_sync(0xffffffffu, rm, 1));
            rm = fmaxf(rm, __shfl_xor_sync(0xffffffffu, rm, 2));
            float mnew = fmaxf(mI[h], rm);
            facr[h] = exp2f(mI[h] - mnew);
            mI[h] = mnew;

            float rs = 0.0f;
            #pragma unroll
            for (int j = 0; j < 8; j++) {
                __half2 xh2 = __floats2half2_rn(s[j][2 * h] - mnew,
                                                s[j][2 * h + 1] - mnew);
                uint32_t px = h2exp2(*(uint32_t*)&xh2);
                ph[j][h] = px;
                float2 pf = __half22float2(*(__half2*)&px);
                rs += pf.x + pf.y;
            }
            rs += __shfl_xor_sync(0xffffffffu, rs, 1);
            rs += __shfl_xor_sync(0xffffffffu, rs, 2);
            lI[h] = lI[h] * facr[h] + rs;
        }

        // ---- rescale O, then O += P V (fully unrolled, ldmatrix B) ----
        #pragma unroll
        for (int j = 0; j < 8; j++) {
            o[j][0] *= facr[0]; o[j][1] *= facr[0];
            o[j][2] *= facr[1]; o[j][3] *= facr[1];
        }
        #pragma unroll
        for (int kc = 0; kc < 4; kc++) {
            const uint32_t kofs = (kc << 4) * 2;
            uint32_t a0 = ph[2 * kc][0],     a1 = ph[2 * kc][1];
            uint32_t a2 = ph[2 * kc + 1][0], a3 = ph[2 * kc + 1][1];
            #pragma unroll
            for (int p = 0; p < 4; p++) {
                uint32_t b0, b1, b2, b3;
                LDSM_X4(b0, b1, b2, b3, vbase + p * (16 * KP * 2) + kofs);
                mma_f16(o[2 * p],     a0, a1, a2, a3, b0, b1);
                mma_f16(o[2 * p + 1], a0, a1, a2, a3, b2, b3);
            }
        }
    }

    // ---- epilogue: Ctxh[b][q][h*64+hd] = half(o / l) ----
    const int b  = bh >> 4;
    const int hh = bh & 15;
    #pragma unroll
    for (int h = 0; h < 2; h++) {
        const float inv = 1.0f / lI[h];
        const int qrow = q0 + 16 * w + fr + 8 * h;
        __half* dst = Out + ((size_t)(b * S_LEN + qrow)) * D_DIM + hh * HD_DIM;
        #pragma unroll
        for (int jh = 0; jh < 8; jh++) {
            __half2 v = __floats2half2_rn(o[jh][2 * h] * inv, o[jh][2 * h + 1] * inv);
            *(__half2*)&dst[8 * jh + 2 * fc] = v;
        }
    }
}

// ---------------------------------------------------------------------------
// Launch
// ---------------------------------------------------------------------------
extern "C" void kernel_launch(void* const* d_in, const int* in_sizes, int n_in,
                              void* d_out, int out_size)
{
    const float* x  = (const float*)d_in[0];
    // d_in[1] = mask — reproduced analytically in-kernel
    const float* wq = (const float*)d_in[2];
    const float* bq = (const float*)d_in[3];
    const float* wk = (const float*)d_in[4];
    const float* bk = (const float*)d_in[5];
    const float* wv = (const float*)d_in[6];
    const float* bv = (const float*)d_in[7];
    const float* wo = (const float*)d_in[8];
    const float* bo = (const float*)d_in[9];
    float* out = (float*)d_out;

    __half *xh, *wth, *Qh, *Kh, *VTh, *Ctxh;
    cudaGetSymbolAddress((void**)&xh,   g_xh);
    cudaGetSymbolAddress((void**)&wth,  g_WTh);
    cudaGetSymbolAddress((void**)&Qh,   g_Qh);
    cudaGetSymbolAddress((void**)&Kh,   g_Kh);
    cudaGetSymbolAddress((void**)&VTh,  g_VTh);
    cudaGetSymbolAddress((void**)&Ctxh, g_Ctxh);

    cudaFuncSetAttribute(gemm_f16_kernel,
                         cudaFuncAttributeMaxDynamicSharedMemorySize,
                         GEMM_SMEM_BYTES);
    cudaFuncSetAttribute(flash_f16_kernel,
                         cudaFuncAttributeMaxDynamicSharedMemorySize,
                         FLASH_SMEM_BYTES);

    // 1. fused prep: x -> fp16  +  weight transpose -> fp16
    prep_kernel<<<8192, 256>>>(x, xh, wq, wk, wv, wo, wth);

    // 2. fused QKV projection in ONE launch (1536 CTAs)
    gemm_f16_kernel<<<1536, 128, GEMM_SMEM_BYTES>>>(
        xh, wth, bq, bk, bv, nullptr, Qh, Kh, VTh, 3);

    // 3. attention (fp16 flash, 4 CTAs/SM, ldmatrix, f16x2 exp2)
    flash_f16_kernel<<<dim3(S_LEN / 64, B_NUM * H_NUM), 128, FLASH_SMEM_BYTES>>>(
        Qh, Kh, VTh, Ctxh);

    // 4. output projection (f32 out)
    gemm_f16_kernel<<<dim3(D_DIM / 128, M_TOT / 64), 128, GEMM_SMEM_BYTES>>>(
        Ctxh, wth + (size_t)3 * D_DIM * D_DIM, bo, nullptr, nullptr,
        out, nullptr, nullptr, nullptr, 0);
}